// round 1
// baseline (speedup 1.0000x reference)
#include <cuda_runtime.h>

#define CH_IN 32
#define CH_Y  16
#define IMG_H 256
#define IMG_W 256
#define NB    16
#define CHS   (IMG_H * IMG_W)   // channel stride in elements

// One block per (b, h) row. 256 threads = one thread per w.
// Per thread: q[16], k[16], v[16] accumulated in registers from 32 input
// channels; softmax over w via block reduction; 32-channel output conv;
// c written through to the concat half during the load pass.
__global__ void __launch_bounds__(IMG_W) cross_attn_kernel(
    const float* __restrict__ cin, const float* __restrict__ pin,
    const float* __restrict__ Wq,  const float* __restrict__ bq,
    const float* __restrict__ Wk,  const float* __restrict__ bk,
    const float* __restrict__ Wv,  const float* __restrict__ bv,
    const float* __restrict__ Wy,  const float* __restrict__ by,
    float* __restrict__ out)
{
    // Weights in smem as float4 so each LDS.128 (broadcast) feeds 4 FMAs.
    __shared__ float4 wq_s[CH_Y * CH_IN / 4];   // [16][8]
    __shared__ float4 wk_s[CH_Y * CH_IN / 4];
    __shared__ float4 wv_s[CH_Y * CH_IN / 4];
    __shared__ float4 wy_s[CH_IN * CH_Y / 4];   // [32][4]
    __shared__ float  bq_s[CH_Y], bk_s[CH_Y], bv_s[CH_Y], by_s[CH_IN];
    __shared__ float  red[8][CH_Y];             // per-warp partial sums

    const int tid = threadIdx.x;

    if (tid < CH_Y * CH_IN / 4) {               // 128 threads load 4 weight mats
        wq_s[tid] = ((const float4*)Wq)[tid];
        wk_s[tid] = ((const float4*)Wk)[tid];
        wv_s[tid] = ((const float4*)Wv)[tid];
        wy_s[tid] = ((const float4*)Wy)[tid];
    }
    if (tid < CH_Y)  { bq_s[tid] = bq[tid]; bk_s[tid] = bk[tid]; bv_s[tid] = bv[tid]; }
    if (tid < CH_IN) { by_s[tid] = by[tid]; }
    __syncthreads();

    const int h = blockIdx.x;
    const int b = blockIdx.y;

    const float* cp = cin + (size_t)b * CH_IN * CHS + (size_t)h * IMG_W + tid;
    const float* pp = pin + (size_t)b * CH_IN * CHS + (size_t)h * IMG_W + tid;
    float* oy = out + (size_t)b * 2 * CH_IN * CHS + (size_t)h * IMG_W + tid;
    float* oc = oy + (size_t)CH_IN * CHS;       // concat(c) half

    float q[CH_Y], k[CH_Y], v[CH_Y];
#pragma unroll
    for (int o = 0; o < CH_Y; o++) { q[o] = bq_s[o]; k[o] = bk_s[o]; v[o] = bv_s[o]; }

    // Main projection loop: 4 channels per iteration.
#pragma unroll 2
    for (int c4 = 0; c4 < CH_IN / 4; c4++) {
        float cv[4], pv[4];
#pragma unroll
        for (int j = 0; j < 4; j++) {
            cv[j] = cp[(size_t)(c4 * 4 + j) * CHS];
            pv[j] = pp[(size_t)(c4 * 4 + j) * CHS];
        }
#pragma unroll
        for (int j = 0; j < 4; j++) {
            oc[(size_t)(c4 * 4 + j) * CHS] = cv[j];   // write-through concat copy
        }
#pragma unroll
        for (int o = 0; o < CH_Y; o++) {
            float4 a = wq_s[o * (CH_IN / 4) + c4];
            q[o] += a.x * cv[0] + a.y * cv[1] + a.z * cv[2] + a.w * cv[3];
            float4 bkk = wk_s[o * (CH_IN / 4) + c4];
            k[o] += bkk.x * pv[0] + bkk.y * pv[1] + bkk.z * pv[2] + bkk.w * pv[3];
            float4 cvv = wv_s[o * (CH_IN / 4) + c4];
            v[o] += cvv.x * pv[0] + cvv.y * pv[1] + cvv.z * pv[2] + cvv.w * pv[3];
        }
    }

    // exp(q*k); softmax over w = block reduction over 256 threads.
    // No max-subtraction needed: |q*k| is O(1..10), exp is safe in fp32 and
    // the normalized result is mathematically identical to stable softmax.
    float e[CH_Y];
#pragma unroll
    for (int o = 0; o < CH_Y; o++) e[o] = __expf(q[o] * k[o]);

    const int lane = tid & 31;
    const int wrp  = tid >> 5;
#pragma unroll
    for (int o = 0; o < CH_Y; o++) {
        float s = e[o];
#pragma unroll
        for (int d = 16; d > 0; d >>= 1) s += __shfl_xor_sync(0xffffffffu, s, d);
        if (lane == 0) red[wrp][o] = s;
    }
    __syncthreads();

    float y[CH_Y];
#pragma unroll
    for (int o = 0; o < CH_Y; o++) {
        float s = red[0][o] + red[1][o] + red[2][o] + red[3][o]
                + red[4][o] + red[5][o] + red[6][o] + red[7][o];
        y[o] = e[o] * __frcp_rn(s) * v[o];      // softmax(q*k) * v
    }

    // Output conv1x1: y2[ic] = by[ic] + sum_o Wy[ic][o] * y[o]
#pragma unroll
    for (int ic = 0; ic < CH_IN; ic++) {
        float acc = by_s[ic];
#pragma unroll
        for (int o4 = 0; o4 < CH_Y / 4; o4++) {
            float4 w4 = wy_s[ic * (CH_Y / 4) + o4];
            acc += w4.x * y[o4 * 4 + 0] + w4.y * y[o4 * 4 + 1]
                 + w4.z * y[o4 * 4 + 2] + w4.w * y[o4 * 4 + 3];
        }
        oy[(size_t)ic * CHS] = acc;
    }
}

extern "C" void kernel_launch(void* const* d_in, const int* in_sizes, int n_in,
                              void* d_out, int out_size)
{
    dim3 grid(IMG_H, NB);
    cross_attn_kernel<<<grid, IMG_W>>>(
        (const float*)d_in[0],  // c
        (const float*)d_in[1],  // p
        (const float*)d_in[2],  // Wq
        (const float*)d_in[3],  // bq
        (const float*)d_in[4],  // Wk
        (const float*)d_in[5],  // bk
        (const float*)d_in[6],  // Wv
        (const float*)d_in[7],  // bv
        (const float*)d_in[8],  // Wy
        (const float*)d_in[9],  // by
        (float*)d_out);
}

// round 2
// speedup vs baseline: 1.3342x; 1.3342x over previous
#include <cuda_runtime.h>

#define CH_IN 32
#define CH_Y  16
#define IMG_H 256
#define IMG_W 256
#define NB    16
#define CHS   (IMG_H * IMG_W)        // channel stride in elements
#define CHS4  (CHS / 4)              // in float4
#define ROW_F4 (CH_IN * IMG_W / 4)   // 2048 float4 per tensor-row

// One block per (b,h) row; 256 threads.
// Phase 1: cooperative float4 staging of c-row and p-row into smem (64KB),
//          concat copy of c emitted with STG.128 from the same registers.
// Phase 2: per-thread (one w each) q/k/v projection from smem, width-softmax
//          via block reduction, output conv1x1.
__global__ void __launch_bounds__(IMG_W, 3) cross_attn_kernel(
    const float* __restrict__ cin, const float* __restrict__ pin,
    const float* __restrict__ Wq,  const float* __restrict__ bq,
    const float* __restrict__ Wk,  const float* __restrict__ bk,
    const float* __restrict__ Wv,  const float* __restrict__ bv,
    const float* __restrict__ Wy,  const float* __restrict__ by,
    float* __restrict__ out)
{
    extern __shared__ float smem[];          // [0,8192) = c row, [8192,16384) = p row
    float* sc = smem;
    float* sp = smem + CH_IN * IMG_W;

    __shared__ float4 wq_s[CH_Y * CH_IN / 4];   // [16][8]
    __shared__ float4 wk_s[CH_Y * CH_IN / 4];
    __shared__ float4 wv_s[CH_Y * CH_IN / 4];
    __shared__ float4 wy_s[CH_IN * CH_Y / 4];   // [32][4]
    __shared__ float  bq_s[CH_Y], bk_s[CH_Y], bv_s[CH_Y], by_s[CH_IN];
    __shared__ float  red[8][CH_Y];

    const int tid = threadIdx.x;

    if (tid < CH_Y * CH_IN / 4) {
        wq_s[tid] = ((const float4*)Wq)[tid];
        wk_s[tid] = ((const float4*)Wk)[tid];
        wv_s[tid] = ((const float4*)Wv)[tid];
        wy_s[tid] = ((const float4*)Wy)[tid];
    }
    if (tid < CH_Y)  { bq_s[tid] = bq[tid]; bk_s[tid] = bk[tid]; bv_s[tid] = bv[tid]; }
    if (tid < CH_IN) { by_s[tid] = by[tid]; }

    const int h = blockIdx.x & (IMG_H - 1);
    const int b = blockIdx.x >> 8;

    // ---------------- Phase 1: stage row + concat copy ----------------
    // Thread handles fixed w4 = tid&63, channels ch = i*4 + (tid>>6), i=0..7.
    const int w4 = tid & 63;
    const int chb = tid >> 6;                 // 0..3
    const float4* cg = (const float4*)(cin + (size_t)b * CH_IN * CHS + (size_t)h * IMG_W);
    const float4* pg = (const float4*)(pin + (size_t)b * CH_IN * CHS + (size_t)h * IMG_W);
    float4* ocg = (float4*)(out + (size_t)b * 2 * CH_IN * CHS + (size_t)CH_IN * CHS
                                + (size_t)h * IMG_W);

    float4 cbuf[8], pbuf[8];
#pragma unroll
    for (int i = 0; i < 8; i++) {
        int ch = i * 4 + chb;
        cbuf[i] = cg[(size_t)ch * CHS4 + w4];
        pbuf[i] = pg[(size_t)ch * CHS4 + w4];
    }
#pragma unroll
    for (int i = 0; i < 8; i++) {
        int ch = i * 4 + chb;
        int sidx = ch * (IMG_W / 4) + w4;     // float4 index into row smem
        ((float4*)sc)[sidx] = cbuf[i];
        ((float4*)sp)[sidx] = pbuf[i];
        ocg[(size_t)ch * CHS4 + w4] = cbuf[i];   // concat(c) write-through, STG.128
    }
    __syncthreads();

    // ---------------- Phase 2: projections from smem ----------------
    float q[CH_Y], k[CH_Y], v[CH_Y];
#pragma unroll
    for (int o = 0; o < CH_Y; o++) { q[o] = bq_s[o]; k[o] = bk_s[o]; v[o] = bv_s[o]; }

#pragma unroll
    for (int c4 = 0; c4 < CH_IN / 4; c4++) {
        float cv[4], pv[4];
#pragma unroll
        for (int j = 0; j < 4; j++) {
            cv[j] = sc[(c4 * 4 + j) * IMG_W + tid];   // lane-contiguous: conflict-free
            pv[j] = sp[(c4 * 4 + j) * IMG_W + tid];
        }
#pragma unroll
        for (int o = 0; o < CH_Y; o++) {
            float4 a = wq_s[o * (CH_IN / 4) + c4];
            q[o] += a.x * cv[0] + a.y * cv[1] + a.z * cv[2] + a.w * cv[3];
            float4 bkk = wk_s[o * (CH_IN / 4) + c4];
            k[o] += bkk.x * pv[0] + bkk.y * pv[1] + bkk.z * pv[2] + bkk.w * pv[3];
            float4 cvv = wv_s[o * (CH_IN / 4) + c4];
            v[o] += cvv.x * pv[0] + cvv.y * pv[1] + cvv.z * pv[2] + cvv.w * pv[3];
        }
    }

    // softmax over width (block reduction). No max-subtraction needed:
    // |q*k| is O(1..10); fp32 exp is safe and result identical after normalize.
    float e[CH_Y];
#pragma unroll
    for (int o = 0; o < CH_Y; o++) e[o] = __expf(q[o] * k[o]);

    const int lane = tid & 31;
    const int wrp  = tid >> 5;
#pragma unroll
    for (int o = 0; o < CH_Y; o++) {
        float s = e[o];
#pragma unroll
        for (int d = 16; d > 0; d >>= 1) s += __shfl_xor_sync(0xffffffffu, s, d);
        if (lane == 0) red[wrp][o] = s;
    }
    __syncthreads();

    float y[CH_Y];
#pragma unroll
    for (int o = 0; o < CH_Y; o++) {
        float s = red[0][o] + red[1][o] + red[2][o] + red[3][o]
                + red[4][o] + red[5][o] + red[6][o] + red[7][o];
        y[o] = e[o] * __frcp_rn(s) * v[o];
    }

    // Output conv1x1
    float* oy = out + (size_t)b * 2 * CH_IN * CHS + (size_t)h * IMG_W + tid;
#pragma unroll
    for (int ic = 0; ic < CH_IN; ic++) {
        float acc = by_s[ic];
#pragma unroll
        for (int o4 = 0; o4 < CH_Y / 4; o4++) {
            float4 w4v = wy_s[ic * (CH_Y / 4) + o4];
            acc += w4v.x * y[o4 * 4 + 0] + w4v.y * y[o4 * 4 + 1]
                 + w4v.z * y[o4 * 4 + 2] + w4v.w * y[o4 * 4 + 3];
        }
        oy[(size_t)ic * CHS] = acc;
    }
}

extern "C" void kernel_launch(void* const* d_in, const int* in_sizes, int n_in,
                              void* d_out, int out_size)
{
    const int dyn_smem = CH_IN * IMG_W * 2 * sizeof(float);   // 64 KB
    cudaFuncSetAttribute(cross_attn_kernel,
                         cudaFuncAttributeMaxDynamicSharedMemorySize, dyn_smem);
    cross_attn_kernel<<<NB * IMG_H, IMG_W, dyn_smem>>>(
        (const float*)d_in[0],  // c
        (const float*)d_in[1],  // p
        (const float*)d_in[2],  // Wq
        (const float*)d_in[3],  // bq
        (const float*)d_in[4],  // Wk
        (const float*)d_in[5],  // bk
        (const float*)d_in[6],  // Wv
        (const float*)d_in[7],  // bv
        (const float*)d_in[8],  // Wy
        (const float*)d_in[9],  // by
        (float*)d_out);
}

// round 3
// speedup vs baseline: 1.6511x; 1.2375x over previous
#include <cuda_runtime.h>

#define CH_IN 32
#define CH_Y  16
#define IMG_H 256
#define IMG_W 256
#define NB    16
#define CHS   (IMG_H * IMG_W)   // channel stride (elements)
#define CHS4  (CHS / 4)
#define CHS2  (CHS / 2)
#define NT    128               // threads per block; one (b,h) row per block

// One block per (b,h) row; 128 threads, 2 pixels (w = 2*tid, 2*tid+1) each.
// Phase 1: concat write-through of c (LDG.128->STG.128), stage p row in smem.
// Phase 2: q,k projection (c from global LDG.64, p from smem), exp, width
//          softmax reduction, fold 1/sum into e, v projection pass, out conv.
__global__ void __launch_bounds__(NT, 4) cross_attn_kernel(
    const float* __restrict__ cin, const float* __restrict__ pin,
    const float* __restrict__ Wq,  const float* __restrict__ bq,
    const float* __restrict__ Wk,  const float* __restrict__ bk,
    const float* __restrict__ Wv,  const float* __restrict__ bv,
    const float* __restrict__ Wy,  const float* __restrict__ by,
    float* __restrict__ out)
{
    __shared__ float  sp[CH_IN * IMG_W];        // 32KB: p row, [ch][w]
    __shared__ float4 wq_s[CH_Y * CH_IN / 4];   // 128 x float4
    __shared__ float4 wk_s[CH_Y * CH_IN / 4];
    __shared__ float4 wv_s[CH_Y * CH_IN / 4];
    __shared__ float4 wy_s[CH_IN * CH_Y / 4];   // 128 x float4
    __shared__ float  bq_s[CH_Y], bk_s[CH_Y], bv_s[CH_Y], by_s[CH_IN];
    __shared__ float  red[4][CH_Y];

    const int tid = threadIdx.x;

    // NT == 128 == number of float4 per weight matrix: every thread loads one.
    wq_s[tid] = ((const float4*)Wq)[tid];
    wk_s[tid] = ((const float4*)Wk)[tid];
    wv_s[tid] = ((const float4*)Wv)[tid];
    wy_s[tid] = ((const float4*)Wy)[tid];
    if (tid < CH_Y)  { bq_s[tid] = bq[tid]; bk_s[tid] = bk[tid]; bv_s[tid] = bv[tid]; }
    if (tid < CH_IN) { by_s[tid] = by[tid]; }

    const int h = blockIdx.x & (IMG_H - 1);
    const int b = blockIdx.x >> 8;

    const size_t cbase = (size_t)b * CH_IN * CHS + (size_t)h * IMG_W;
    const float4* cg = (const float4*)(cin + cbase);
    const float4* pg = (const float4*)(pin + cbase);
    float4* ocg = (float4*)(out + (size_t)b * 2 * CH_IN * CHS + (size_t)CH_IN * CHS
                                + (size_t)h * IMG_W);
    float4* sp4 = (float4*)sp;

    // ---------------- Phase 1: concat copy of c + stage p ----------------
    // 2048 float4 per tensor-row / 128 threads = 16 each, batched 8 for MLP.
#pragma unroll
    for (int half = 0; half < 2; half++) {
        float4 cb[8], pb[8];
#pragma unroll
        for (int i = 0; i < 8; i++) {
            int idx = tid + (half * 8 + i) * NT;            // = ch*64 + w4
            int ch = idx >> 6, w4 = idx & 63;
            cb[i] = cg[(size_t)ch * CHS4 + w4];
            pb[i] = pg[(size_t)ch * CHS4 + w4];
        }
#pragma unroll
        for (int i = 0; i < 8; i++) {
            int idx = tid + (half * 8 + i) * NT;
            int ch = idx >> 6, w4 = idx & 63;
            ocg[(size_t)ch * CHS4 + w4] = cb[i];            // concat(c) half
            sp4[idx] = pb[i];                               // p stays in smem
        }
    }
    __syncthreads();

    // ---------------- Phase 2a: q,k projection ----------------
    const float2* cp2 = (const float2*)(cin + cbase);       // + ch*CHS2 + tid
    const float2* sp2 = (const float2*)sp;                  // + ch*128 + tid

    float2 q2[CH_Y], k2[CH_Y];
#pragma unroll
    for (int o = 0; o < CH_Y; o++) {
        q2[o].x = q2[o].y = bq_s[o];
        k2[o].x = k2[o].y = bk_s[o];
    }

#pragma unroll
    for (int c4 = 0; c4 < CH_IN / 4; c4++) {
        float2 cv[4], pv[4];
#pragma unroll
        for (int j = 0; j < 4; j++) {
            int ch = c4 * 4 + j;
            cv[j] = cp2[(size_t)ch * CHS2 + tid];           // L2-resident re-read
            pv[j] = sp2[ch * (IMG_W / 2) + tid];
        }
#pragma unroll
        for (int o = 0; o < CH_Y; o++) {
            float4 a = wq_s[o * (CH_IN / 4) + c4];
            q2[o].x += a.x * cv[0].x + a.y * cv[1].x + a.z * cv[2].x + a.w * cv[3].x;
            q2[o].y += a.x * cv[0].y + a.y * cv[1].y + a.z * cv[2].y + a.w * cv[3].y;
            float4 wk4 = wk_s[o * (CH_IN / 4) + c4];
            k2[o].x += wk4.x * pv[0].x + wk4.y * pv[1].x + wk4.z * pv[2].x + wk4.w * pv[3].x;
            k2[o].y += wk4.x * pv[0].y + wk4.y * pv[1].y + wk4.z * pv[2].y + wk4.w * pv[3].y;
        }
    }

    // exp(q*k). No max-subtraction: |q*k| is O(1..10), fp32 exp is safe and
    // the normalized softmax is mathematically identical.
    float2 e2[CH_Y];
#pragma unroll
    for (int o = 0; o < CH_Y; o++) {
        e2[o].x = __expf(q2[o].x * k2[o].x);
        e2[o].y = __expf(q2[o].y * k2[o].y);
    }

    // ---------------- softmax reduction over width ----------------
    const int lane = tid & 31;
    const int wrp  = tid >> 5;
#pragma unroll
    for (int o = 0; o < CH_Y; o++) {
        float s = e2[o].x + e2[o].y;
#pragma unroll
        for (int d = 16; d > 0; d >>= 1) s += __shfl_xor_sync(0xffffffffu, s, d);
        if (lane == 0) red[wrp][o] = s;
    }
    __syncthreads();
#pragma unroll
    for (int o = 0; o < CH_Y; o++) {
        float inv = __frcp_rn(red[0][o] + red[1][o] + red[2][o] + red[3][o]);
        e2[o].x *= inv;                                     // fold 1/sum into e
        e2[o].y *= inv;
    }

    // ---------------- Phase 2b: v projection ----------------
    float2 v2[CH_Y];
#pragma unroll
    for (int o = 0; o < CH_Y; o++) v2[o].x = v2[o].y = bv_s[o];

#pragma unroll
    for (int c4 = 0; c4 < CH_IN / 4; c4++) {
        float2 pv[4];
#pragma unroll
        for (int j = 0; j < 4; j++)
            pv[j] = sp2[(c4 * 4 + j) * (IMG_W / 2) + tid];
#pragma unroll
        for (int o = 0; o < CH_Y; o++) {
            float4 wv4 = wv_s[o * (CH_IN / 4) + c4];
            v2[o].x += wv4.x * pv[0].x + wv4.y * pv[1].x + wv4.z * pv[2].x + wv4.w * pv[3].x;
            v2[o].y += wv4.x * pv[0].y + wv4.y * pv[1].y + wv4.z * pv[2].y + wv4.w * pv[3].y;
        }
    }

    // y = softmax(q*k) * v  (normalization already folded into e2)
#pragma unroll
    for (int o = 0; o < CH_Y; o++) {
        e2[o].x *= v2[o].x;
        e2[o].y *= v2[o].y;
    }

    // ---------------- output conv1x1 ----------------
    float2* oy2 = (float2*)(out + (size_t)b * 2 * CH_IN * CHS + (size_t)h * IMG_W);
#pragma unroll
    for (int ic = 0; ic < CH_IN; ic++) {
        float2 acc;
        acc.x = acc.y = by_s[ic];
#pragma unroll
        for (int o4 = 0; o4 < CH_Y / 4; o4++) {
            float4 w4 = wy_s[ic * (CH_Y / 4) + o4];
            acc.x += w4.x * e2[o4*4+0].x + w4.y * e2[o4*4+1].x
                   + w4.z * e2[o4*4+2].x + w4.w * e2[o4*4+3].x;
            acc.y += w4.x * e2[o4*4+0].y + w4.y * e2[o4*4+1].y
                   + w4.z * e2[o4*4+2].y + w4.w * e2[o4*4+3].y;
        }
        oy2[(size_t)ic * CHS2 + tid] = acc;
    }
}

extern "C" void kernel_launch(void* const* d_in, const int* in_sizes, int n_in,
                              void* d_out, int out_size)
{
    cross_attn_kernel<<<NB * IMG_H, NT>>>(
        (const float*)d_in[0],  // c
        (const float*)d_in[1],  // p
        (const float*)d_in[2],  // Wq
        (const float*)d_in[3],  // bq
        (const float*)d_in[4],  // Wk
        (const float*)d_in[5],  // bk
        (const float*)d_in[6],  // Wv
        (const float*)d_in[7],  // bv
        (const float*)d_in[8],  // Wy
        (const float*)d_in[9],  // by
        (float*)d_out);
}